// round 9
// baseline (speedup 1.0000x reference)
#include <cuda_runtime.h>

#define BB 256
#define TT 256
#define HH 16
#define DD 88
#define LOG16F 2.7725887222397811f

// table halves: even half d=0..43 at [d*80 + c*20 + h]; odd half d=44..87 at
// [3536 + (d-44)*80 + c*20 + h]. 3536 % 32 == 16 -> the two halves hit
// disjoint bank quartets ({0,20,8,28} vs {16,4,24,12}) -> conflict-free.
#define HALF_OFF 3536
#define TAB_FLOATS (HALF_OFF + 44 * 80)   // 7056

__device__ float g_part[BB];
__device__ unsigned int g_ticket;         // zero-init; wraps via atomicInc

#define ADD_F32X2(out, a, b) \
    asm("add.rn.f32x2 %0, %1, %2;" : "=l"(out) : "l"(a), "l"(b))

__device__ __forceinline__ unsigned pack4(float4 v) {
    return (v.x > 0.5f ? 1u : 0u) | (v.y > 0.5f ? 2u : 0u) |
           (v.z > 0.5f ? 4u : 0u) | (v.w > 0.5f ? 8u : 0u);
}

__global__ void __launch_bounds__(512, 2)
fused_hmm(const float* __restrict__ seq, const int* __restrict__ lengths,
          const float* __restrict__ px, const float* __restrict__ py,
          float* __restrict__ out) {
    // 28224 + 16384 + 1024 + 3084 + 64 = 48780 B (< 48 KB static limit)
    __shared__ __align__(16) float sTab[TAB_FLOATS];
    __shared__ __align__(16) float sE[TT * HH];     // exp(emit - m)
    __shared__ float sMe[TT];                       // per-t emit max
    __shared__ unsigned sPack[(TT + 1) * 3];        // y bits, row t+1; row0 = 0
    __shared__ volatile unsigned sFlag[16];         // per-16t-chunk ready flags

    const int b = blockIdx.x;
    const int tid = threadIdx.x;
    const int lane = tid & 31;
    const int wid = tid >> 5;          // 0..15
    const int L = lengths[b];

    if (tid < 3) sPack[tid] = 0u;      // yprev row for t = 0
    if (tid < 16) sFlag[tid] = 0u;

    // ---- emission log-table (fast __logf; split-half padded layout) ----
    for (int e = tid; e < 4 * DD * HH; e += 512) {
        int h = e & 15;
        int rem = e >> 4;
        int d = rem % DD;
        int c = rem / DD;
        int yp = c >> 1, yb = c & 1;
        float p = py[(h * 2 + yp) * DD + d];
        float v = yb ? __logf(p) : __logf(1.0f - p);
        int addr = (d < 44) ? (d * 80 + c * 20 + h)
                            : (HALF_OFF + (d - 44) * 80 + c * 20 + h);
        sTab[addr] = v;
    }

    // ---- ballot-free bit-pack: thread builds one word from float4 loads ----
    {
        const float* sb = seq + (size_t)b * TT * DD;
#pragma unroll
        for (int rep = 0; rep < 2; rep++) {
            int idx = tid + rep * 512;
            if (idx < TT * 3) {
                int t = idx / 3;
                int w = idx - t * 3;
                const float4* src = reinterpret_cast<const float4*>(sb + t * DD + w * 32);
                float4 v0 = src[0], v1 = src[1], v2 = src[2];
                float4 v3 = src[3], v4 = src[4], v5 = src[5];
                unsigned bits = pack4(v0) | (pack4(v1) << 4) | (pack4(v2) << 8) |
                                (pack4(v3) << 12) | (pack4(v4) << 16) | (pack4(v5) << 20);
                if (w < 2) {
                    float4 v6 = src[6], v7 = src[7];
                    bits |= (pack4(v6) << 24) | (pack4(v7) << 28);
                }
                sPack[(t + 1) * 3 + w] = bits;
            }
        }
    }
    __syncthreads();

    // ---- emit: warp w covers t = w*16..w*16+15; lane pair (2k,2k+1) = one t ----
    {
        const int k = lane >> 1;
        const int half = lane & 1;     // d half: 0 -> d 0..43, 1 -> d 44..87
        const int t = wid * 16 + k;

        const unsigned* pk = &sPack[t * 3];          // rows t (yprev), t+1 (y)
        unsigned p0 = pk[0], p1 = pk[1], p2 = pk[2];
        unsigned y0 = pk[3], y1 = pk[4], y2 = pk[5];

        unsigned long long Y, P;
        if (half == 0) {
            Y = (unsigned long long)y0 | ((unsigned long long)y1 << 32);
            P = (unsigned long long)p0 | ((unsigned long long)p1 << 32);
        } else {
            Y = ((unsigned long long)y1 >> 12) | ((unsigned long long)y2 << 20);
            P = ((unsigned long long)p1 >> 12) | ((unsigned long long)p2 << 20);
        }
        const float* tbase = sTab + half * HALF_OFF;

        unsigned long long acc2[8];
#pragma unroll
        for (int q = 0; q < 8; q++) acc2[q] = 0ull;

        // run unconditionally (keeps warp converged for the shfl combine)
#pragma unroll 4
        for (int i = 0; i < 44; i++) {
            unsigned code = ((unsigned)((P >> i) & 1ull) << 1) | (unsigned)((Y >> i) & 1ull);
            const ulonglong2* p2v = reinterpret_cast<const ulonglong2*>(tbase + i * 80 + code * 20);
            ulonglong2 q0 = p2v[0], q1 = p2v[1], q2 = p2v[2], q3 = p2v[3];
            ADD_F32X2(acc2[0], acc2[0], q0.x);
            ADD_F32X2(acc2[1], acc2[1], q0.y);
            ADD_F32X2(acc2[2], acc2[2], q1.x);
            ADD_F32X2(acc2[3], acc2[3], q1.y);
            ADD_F32X2(acc2[4], acc2[4], q2.x);
            ADD_F32X2(acc2[5], acc2[5], q2.y);
            ADD_F32X2(acc2[6], acc2[6], q3.x);
            ADD_F32X2(acc2[7], acc2[7], q3.y);
        }

        float acc[16];
#pragma unroll
        for (int q = 0; q < 8; q++) {
            unsigned lo, hi;
            asm("mov.b64 {%0, %1}, %2;" : "=r"(lo), "=r"(hi) : "l"(acc2[q]));
            acc[2 * q]     = __uint_as_float(lo);
            acc[2 * q + 1] = __uint_as_float(hi);
        }
        // combine the two d-halves within the lane pair
#pragma unroll
        for (int h = 0; h < 16; h++)
            acc[h] += __shfl_xor_sync(0xffffffffu, acc[h], 1);

        if (t < L) {
            float m = acc[0];
#pragma unroll
            for (int h = 1; h < 16; h++) m = fmaxf(m, acc[h]);

            const int hb = half * 8;   // even lane writes h 0..7, odd h 8..15
            float4 e0, e1;
            e0.x = __expf(acc[hb + 0] - m);
            e0.y = __expf(acc[hb + 1] - m);
            e0.z = __expf(acc[hb + 2] - m);
            e0.w = __expf(acc[hb + 3] - m);
            e1.x = __expf(acc[hb + 4] - m);
            e1.y = __expf(acc[hb + 5] - m);
            e1.z = __expf(acc[hb + 6] - m);
            e1.w = __expf(acc[hb + 7] - m);
            float4* eo = reinterpret_cast<float4*>(sE + t * 16 + hb);
            eo[0] = e0;
            eo[1] = e1;
            if (half == 0) sMe[t] = m;
        }

        __threadfence_block();
        __syncwarp();
        if (lane == 0) sFlag[wid] = 1u;   // chunk wid ready
    }

    // ---- serial forward scan (warp 0), pipelined against emit via flags ----
    if (wid == 0) {
        const int j = lane & 15;
        float Pc[16];
#pragma unroll
        for (int i = 0; i < 16; i++) Pc[i] = px[i * 16 + j];

        float a = (j == 0) ? 1.f : 0.f;   // alpha0 one-hot at state 0
        float C = 0.f;

        for (int c = 0; c < 16 && c * 16 < L; c++) {
            if (c) {
                while (sFlag[c] == 0u) __nanosleep(64);
                __threadfence_block();
            }
            const int t0 = c * 16;
            const int t1 = (t0 + 16 < L) ? (t0 + 16) : L;

            float ec = sE[t0 * 16 + j];
            float mc = sMe[t0];
            for (int t = t0; t < t1; t++) {
                float ecn = 1.f, mcn = 0.f;
                if (t + 1 < t1) {                    // prefetch off the dep chain
                    ecn = sE[(t + 1) * 16 + j];
                    mcn = sMe[t + 1];
                }
                float a0 = 0.f, a1 = 0.f, a2 = 0.f, a3 = 0.f;
#pragma unroll
                for (int i = 0; i < 16; i += 4) {
                    a0 = fmaf(__shfl_sync(0xffffffffu, a, i),     Pc[i],     a0);
                    a1 = fmaf(__shfl_sync(0xffffffffu, a, i + 1), Pc[i + 1], a1);
                    a2 = fmaf(__shfl_sync(0xffffffffu, a, i + 2), Pc[i + 2], a2);
                    a3 = fmaf(__shfl_sync(0xffffffffu, a, i + 3), Pc[i + 3], a3);
                }
                a = ((a0 + a1) + (a2 + a3)) * ec;
                C += mc;

                if ((t & 15) == 15) {                // renorm every 16 steps
                    float m = a;
                    m = fmaxf(m, __shfl_xor_sync(0xffffffffu, m, 8));
                    m = fmaxf(m, __shfl_xor_sync(0xffffffffu, m, 4));
                    m = fmaxf(m, __shfl_xor_sync(0xffffffffu, m, 2));
                    m = fmaxf(m, __shfl_xor_sync(0xffffffffu, m, 1));
                    a = __fdividef(a, m);
                    C += __logf(m);
                }
                ec = ecn;
                mc = mcn;
            }
        }

        float s = a;
        s += __shfl_xor_sync(0xffffffffu, s, 8);
        s += __shfl_xor_sync(0xffffffffu, s, 4);
        s += __shfl_xor_sync(0xffffffffu, s, 2);
        s += __shfl_xor_sync(0xffffffffu, s, 1);

        float res = C + logf(s) + (float)(TT - L) * LOG16F;

        // ---- in-kernel deterministic final reduction (last block) ----
        unsigned lastFlag = 0;
        if (lane == 0) {
            g_part[b] = res;
            __threadfence();
            unsigned old = atomicInc(&g_ticket, BB - 1);   // wraps to 0 at 255
            lastFlag = (old == BB - 1) ? 1u : 0u;
        }
        lastFlag = __shfl_sync(0xffffffffu, lastFlag, 0);
        if (lastFlag) {
            __threadfence();
            float s2 = 0.f;
#pragma unroll
            for (int i = 0; i < BB / 32; i++)
                s2 += *((volatile float*)&g_part[i * 32 + lane]);
            s2 += __shfl_xor_sync(0xffffffffu, s2, 16);
            s2 += __shfl_xor_sync(0xffffffffu, s2, 8);
            s2 += __shfl_xor_sync(0xffffffffu, s2, 4);
            s2 += __shfl_xor_sync(0xffffffffu, s2, 2);
            s2 += __shfl_xor_sync(0xffffffffu, s2, 1);
            if (lane == 0) out[0] = s2;
        }
    }
}

extern "C" void kernel_launch(void* const* d_in, const int* in_sizes, int n_in,
                              void* d_out, int out_size) {
    const float* seq     = (const float*)d_in[0];  // (B,T,D) float32
    const int*   lengths = (const int*)  d_in[1];  // (B,)    int32
    const float* probs_x = (const float*)d_in[2];  // (H,H)   float32
    const float* probs_y = (const float*)d_in[3];  // (H,2,D) float32

    fused_hmm<<<BB, 512>>>(seq, lengths, probs_x, probs_y, (float*)d_out);
}

// round 10
// speedup vs baseline: 1.2260x; 1.2260x over previous
#include <cuda_runtime.h>

#define BB 256
#define TT 256
#define HH 16
#define DD 88
#define LOG16F 2.7725887222397811f

// table halves: even half d=0..43 at [d*80 + c*20 + h]; odd half d=44..87 at
// [3536 + ...]. 3536 % 32 == 16 -> halves hit disjoint bank quartets.
#define HALF_OFF 3536
#define TAB_FLOATS (HALF_OFF + 44 * 80)   // 7056

// dynamic smem layout (float offsets)
#define OFF_TAB 0                          // 7056
#define OFF_E   7056                       // 2 * 4096
#define OFF_ME  15248                      // 2 * 256
#define OFF_PK  15760                      // u32: 2 * 772
#define OFF_FLG 17304                      // u32: 32 flags
#define OFF_VW  17336                      // 2 * 16 floats (backward vectors)
#define OFF_CB  17368                      // 2 floats (backward C)
#define SMEM_FLOATS 17376
#define SMEM_BYTES (SMEM_FLOATS * 4)

__device__ float g_part[BB];
__device__ unsigned int g_ticket;          // zero-init; wraps via atomicInc

#define ADD_F32X2(out, a, b) \
    asm("add.rn.f32x2 %0, %1, %2;" : "=l"(out) : "l"(a), "l"(b))

__device__ __forceinline__ unsigned pack4(float4 v) {
    return (v.x > 0.5f ? 1u : 0u) | (v.y > 0.5f ? 2u : 0u) |
           (v.z > 0.5f ? 4u : 0u) | (v.w > 0.5f ? 8u : 0u);
}

__device__ __forceinline__ float warp16_max(float m) {
    m = fmaxf(m, __shfl_xor_sync(0xffffffffu, m, 8));
    m = fmaxf(m, __shfl_xor_sync(0xffffffffu, m, 4));
    m = fmaxf(m, __shfl_xor_sync(0xffffffffu, m, 2));
    m = fmaxf(m, __shfl_xor_sync(0xffffffffu, m, 1));
    return m;
}
__device__ __forceinline__ float warp16_sum(float s) {
    s += __shfl_xor_sync(0xffffffffu, s, 8);
    s += __shfl_xor_sync(0xffffffffu, s, 4);
    s += __shfl_xor_sync(0xffffffffu, s, 2);
    s += __shfl_xor_sync(0xffffffffu, s, 1);
    return s;
}

__global__ void __launch_bounds__(1024, 1)
fused_hmm(const float* __restrict__ seq, const int* __restrict__ lengths,
          const float* __restrict__ px, const float* __restrict__ py,
          float* __restrict__ out) {
    extern __shared__ __align__(16) float smem[];
    float*    sTab  = smem + OFF_TAB;
    float*    sE    = smem + OFF_E;     // [q][t][h]
    float*    sMe   = smem + OFF_ME;    // [q][t]
    unsigned* sPack = reinterpret_cast<unsigned*>(smem + OFF_PK);   // [q][257][3]
    volatile unsigned* sFlag = reinterpret_cast<volatile unsigned*>(smem + OFF_FLG);
    float*    sVW   = smem + OFF_VW;    // [q][16]
    float*    sCB   = smem + OFF_CB;    // [q]

    const int tid  = threadIdx.x;
    const int lane = tid & 31;
    const int wid  = tid >> 5;          // 0..31

    if (tid < 3) { sPack[tid] = 0u; sPack[772 + tid] = 0u; }   // yprev rows t=0
    if (tid < 32) sFlag[tid] = 0u;

    // ---- emission log-table (batch-independent, built once per block) ----
    for (int e = tid; e < 4 * DD * HH; e += 1024) {
        int h = e & 15;
        int rem = e >> 4;
        int d = rem % DD;
        int c = rem / DD;
        int yp = c >> 1, yb = c & 1;
        float p = py[(h * 2 + yp) * DD + d];
        float v = yb ? __logf(p) : __logf(1.0f - p);
        int addr = (d < 44) ? (d * 80 + c * 20 + h)
                            : (HALF_OFF + (d - 44) * 80 + c * 20 + h);
        sTab[addr] = v;
    }

    // ---- ballot-free bit-pack for both batches ----
    {
#pragma unroll
        for (int rep = 0; rep < 2; rep++) {
            int idx = tid + rep * 1024;
            if (idx < 2 * TT * 3) {
                int q = (idx >= TT * 3) ? 1 : 0;
                int r = idx - q * (TT * 3);
                int t = r / 3;
                int w = r - t * 3;
                const float* sb = seq + ((size_t)(blockIdx.x * 2 + q)) * TT * DD;
                const float4* src = reinterpret_cast<const float4*>(sb + t * DD + w * 32);
                float4 v0 = src[0], v1 = src[1], v2 = src[2];
                float4 v3 = src[3], v4 = src[4], v5 = src[5];
                unsigned bits = pack4(v0) | (pack4(v1) << 4) | (pack4(v2) << 8) |
                                (pack4(v3) << 12) | (pack4(v4) << 16) | (pack4(v5) << 20);
                if (w < 2) {
                    float4 v6 = src[6], v7 = src[7];
                    bits |= (pack4(v6) << 24) | (pack4(v7) << 28);
                }
                sPack[q * 772 + (t + 1) * 3 + w] = bits;
            }
        }
    }
    __syncthreads();

    // ---- emit: warp = (batch q = wid>>4, chunk cw = wid&15); lane pair = one t ----
    {
        const int q = wid >> 4;
        const int cw = wid & 15;
        const int L = lengths[blockIdx.x * 2 + q];
        const int k = lane >> 1;
        const int half = lane & 1;
        const int t = cw * 16 + k;

        const unsigned* pk = &sPack[q * 772 + t * 3];
        unsigned p0 = pk[0], p1 = pk[1], p2 = pk[2];
        unsigned y0 = pk[3], y1 = pk[4], y2 = pk[5];

        unsigned long long Y, P;
        if (half == 0) {
            Y = (unsigned long long)y0 | ((unsigned long long)y1 << 32);
            P = (unsigned long long)p0 | ((unsigned long long)p1 << 32);
        } else {
            Y = ((unsigned long long)y1 >> 12) | ((unsigned long long)y2 << 20);
            P = ((unsigned long long)p1 >> 12) | ((unsigned long long)p2 << 20);
        }
        const float* tbase = sTab + half * HALF_OFF;

        unsigned long long acc2[8];
#pragma unroll
        for (int qq = 0; qq < 8; qq++) acc2[qq] = 0ull;

#pragma unroll 4
        for (int i = 0; i < 44; i++) {
            unsigned code = ((unsigned)((P >> i) & 1ull) << 1) | (unsigned)((Y >> i) & 1ull);
            const ulonglong2* p2v = reinterpret_cast<const ulonglong2*>(tbase + i * 80 + code * 20);
            ulonglong2 q0 = p2v[0], q1 = p2v[1], q2 = p2v[2], q3 = p2v[3];
            ADD_F32X2(acc2[0], acc2[0], q0.x);
            ADD_F32X2(acc2[1], acc2[1], q0.y);
            ADD_F32X2(acc2[2], acc2[2], q1.x);
            ADD_F32X2(acc2[3], acc2[3], q1.y);
            ADD_F32X2(acc2[4], acc2[4], q2.x);
            ADD_F32X2(acc2[5], acc2[5], q2.y);
            ADD_F32X2(acc2[6], acc2[6], q3.x);
            ADD_F32X2(acc2[7], acc2[7], q3.y);
        }

        float acc[16];
#pragma unroll
        for (int qq = 0; qq < 8; qq++) {
            unsigned lo, hi;
            asm("mov.b64 {%0, %1}, %2;" : "=r"(lo), "=r"(hi) : "l"(acc2[qq]));
            acc[2 * qq]     = __uint_as_float(lo);
            acc[2 * qq + 1] = __uint_as_float(hi);
        }
#pragma unroll
        for (int h = 0; h < 16; h++)
            acc[h] += __shfl_xor_sync(0xffffffffu, acc[h], 1);

        if (t < L) {
            float m = acc[0];
#pragma unroll
            for (int h = 1; h < 16; h++) m = fmaxf(m, acc[h]);

            const int hb = half * 8;
            float4 e0, e1;
            e0.x = __expf(acc[hb + 0] - m);
            e0.y = __expf(acc[hb + 1] - m);
            e0.z = __expf(acc[hb + 2] - m);
            e0.w = __expf(acc[hb + 3] - m);
            e1.x = __expf(acc[hb + 4] - m);
            e1.y = __expf(acc[hb + 5] - m);
            e1.z = __expf(acc[hb + 6] - m);
            e1.w = __expf(acc[hb + 7] - m);
            float4* eo = reinterpret_cast<float4*>(sE + q * 4096 + t * 16 + hb);
            eo[0] = e0;
            eo[1] = e1;
            if (half == 0) sMe[q * 256 + t] = m;
        }

        __threadfence_block();
        __syncwarp();
        if (lane == 0) sFlag[wid] = 1u;
    }

    // ---- bidirectional scan: warps 0..3 = (batch q = wid>>1, dir = wid&1) ----
    if (wid < 4) {
        const int q = wid >> 1;
        const int dir = wid & 1;
        const int bGlob = blockIdx.x * 2 + q;
        const int L = lengths[bGlob];
        const int mid = L >> 1;
        const int j = lane & 15;
        const float* sEq = sE + q * 4096;
        const float* sMq = sMe + q * 256;
        volatile unsigned* flg = sFlag + q * 16;

        if (dir == 0) {
            // forward: u = alpha0^T prod_{t<mid} P diag(e_t)
            float Pc[16];
#pragma unroll
            for (int i = 0; i < 16; i++) Pc[i] = px[i * 16 + j];

            float a = (j == 0) ? 1.f : 0.f;
            float C = 0.f;
            int t = 0;
            for (int c = 0; c * 16 < mid; c++) {
                while (flg[c] == 0u) __nanosleep(32);
                __threadfence_block();
                int t1 = (c * 16 + 16 < mid) ? (c * 16 + 16) : mid;
                float ec = sEq[t * 16 + j];
                float mc = sMq[t];
                for (; t < t1; t++) {
                    float ecn = 1.f, mcn = 0.f;
                    if (t + 1 < t1) {
                        ecn = sEq[(t + 1) * 16 + j];
                        mcn = sMq[t + 1];
                    }
                    float a0 = 0.f, a1 = 0.f, a2 = 0.f, a3 = 0.f;
#pragma unroll
                    for (int i = 0; i < 16; i += 4) {
                        a0 = fmaf(__shfl_sync(0xffffffffu, a, i),     Pc[i],     a0);
                        a1 = fmaf(__shfl_sync(0xffffffffu, a, i + 1), Pc[i + 1], a1);
                        a2 = fmaf(__shfl_sync(0xffffffffu, a, i + 2), Pc[i + 2], a2);
                        a3 = fmaf(__shfl_sync(0xffffffffu, a, i + 3), Pc[i + 3], a3);
                    }
                    a = ((a0 + a1) + (a2 + a3)) * ec;
                    C += mc;
                    if ((t & 15) == 15) {
                        float m = warp16_max(a);
                        a = __fdividef(a, m);
                        C += __logf(m);
                    }
                    ec = ecn;
                    mc = mcn;
                }
            }

            asm volatile("bar.sync %0, %1;" :: "r"(1 + q), "r"(64) : "memory");

            float dv = warp16_sum(a * sVW[q * 16 + j]);
            float res = C + sCB[q] + logf(dv) + (float)(TT - L) * LOG16F;

            // ---- in-kernel deterministic final reduction (last result) ----
            unsigned lastFlag = 0;
            if (lane == 0) {
                g_part[bGlob] = res;
                __threadfence();
                unsigned old = atomicInc(&g_ticket, BB - 1);   // wraps at 255
                lastFlag = (old == BB - 1) ? 1u : 0u;
            }
            lastFlag = __shfl_sync(0xffffffffu, lastFlag, 0);
            if (lastFlag) {
                __threadfence();
                float s2 = 0.f;
#pragma unroll
                for (int i = 0; i < BB / 32; i++)
                    s2 += *((volatile float*)&g_part[i * 32 + lane]);
                s2 += __shfl_xor_sync(0xffffffffu, s2, 16);
                s2 += __shfl_xor_sync(0xffffffffu, s2, 8);
                s2 += __shfl_xor_sync(0xffffffffu, s2, 4);
                s2 += __shfl_xor_sync(0xffffffffu, s2, 2);
                s2 += __shfl_xor_sync(0xffffffffu, s2, 1);
                if (lane == 0) out[0] = s2;
            }
        } else {
            // backward: w = prod_{t>=mid} (P diag(e_t)) * ones, computed descending
            float Pr[16];                       // row j of P
#pragma unroll
            for (int i = 0; i < 16; i++) Pr[i] = px[j * 16 + i];

            float w = 1.f;
            float C = 0.f;
            int cnt = 0;
            int cLo = mid >> 4;
            for (int c = (L - 1) >> 4; c >= cLo; c--) {
                while (flg[c] == 0u) __nanosleep(32);
                __threadfence_block();
                int tHi = ((c * 16 + 16 < L) ? (c * 16 + 16) : L) - 1;
                int tLo = (c * 16 > mid) ? (c * 16) : mid;
                float ec = sEq[tHi * 16 + j];
                float mc = sMq[tHi];
                for (int t = tHi; t >= tLo; t--) {
                    float ecn = 1.f, mcn = 0.f;
                    if (t - 1 >= tLo) {
                        ecn = sEq[(t - 1) * 16 + j];
                        mcn = sMq[t - 1];
                    }
                    float s = w * ec;
                    float a0 = 0.f, a1 = 0.f, a2 = 0.f, a3 = 0.f;
#pragma unroll
                    for (int i = 0; i < 16; i += 4) {
                        a0 = fmaf(__shfl_sync(0xffffffffu, s, i),     Pr[i],     a0);
                        a1 = fmaf(__shfl_sync(0xffffffffu, s, i + 1), Pr[i + 1], a1);
                        a2 = fmaf(__shfl_sync(0xffffffffu, s, i + 2), Pr[i + 2], a2);
                        a3 = fmaf(__shfl_sync(0xffffffffu, s, i + 3), Pr[i + 3], a3);
                    }
                    w = (a0 + a1) + (a2 + a3);
                    C += mc;
                    cnt++;
                    if ((cnt & 7) == 0) {       // every 8 (worst-case shrink bound)
                        float m = warp16_max(w);
                        w = __fdividef(w, m);
                        C += __logf(m);
                    }
                    ec = ecn;
                    mc = mcn;
                }
            }
            if (lane < 16) sVW[q * 16 + lane] = w;
            if (lane == 0) sCB[q] = C;
            asm volatile("bar.sync %0, %1;" :: "r"(1 + q), "r"(64) : "memory");
        }
    }
}

extern "C" void kernel_launch(void* const* d_in, const int* in_sizes, int n_in,
                              void* d_out, int out_size) {
    const float* seq     = (const float*)d_in[0];  // (B,T,D) float32
    const int*   lengths = (const int*)  d_in[1];  // (B,)    int32
    const float* probs_x = (const float*)d_in[2];  // (H,H)   float32
    const float* probs_y = (const float*)d_in[3];  // (H,2,D) float32

    cudaFuncSetAttribute(fused_hmm, cudaFuncAttributeMaxDynamicSharedMemorySize, SMEM_BYTES);
    fused_hmm<<<BB / 2, 1024, SMEM_BYTES>>>(seq, lengths, probs_x, probs_y, (float*)d_out);
}